// round 13
// baseline (speedup 1.0000x reference)
#include <cuda_runtime.h>
#include <cuda_bf16.h>
#include <cstdint>

#define NN 50000
#define EE 600000
#define DH 128
#define GG 64
#define LL 3
#define ETOT (EE + NN)

// ---------------- scratch (device globals; referenced by name only) --------
__device__ float    g_h[NN * DH];     // node features fp32 (residual stream)
__device__ uint32_t g_hpb[NN * 64];   // projected features as packed bf16x2
__device__ float    g_esrc[NN];
__device__ float    g_edst[NN];
__device__ int      g_rowptr[NN + 1];
__device__ int      g_cnt[NN];
__device__ int      g_col[ETOT];
__device__ float    g_pooled[GG * DH];
// W fragments for mma.m16n8k8 tf32, B-operand layout:
// [mat(4)][ntile(16)][kstep(16)][lane(32)] -> uint2{b0,b1}
__device__ uint2 g_wfrag[4 * 16 * 16 * 32];

// ---------------- helpers --------------------------------------------------
__device__ __forceinline__ uint32_t f2tf32(float f) {
    uint32_t r;
    asm("cvt.rna.tf32.f32 %0, %1;" : "=r"(r) : "f"(f));
    return r;
}

__device__ __forceinline__ void mma_tf32(
    float& c0, float& c1, float& c2, float& c3,
    uint32_t a0, uint32_t a1, uint32_t a2, uint32_t a3,
    uint32_t b0, uint32_t b1)
{
    asm volatile(
        "mma.sync.aligned.m16n8k8.row.col.f32.tf32.tf32.f32 "
        "{%0,%1,%2,%3}, {%4,%5,%6,%7}, {%8,%9}, {%0,%1,%2,%3};\n"
        : "+f"(c0), "+f"(c1), "+f"(c2), "+f"(c3)
        : "r"(a0), "r"(a1), "r"(a2), "r"(a3), "r"(b0), "r"(b1));
}

__device__ __forceinline__ float leaky(float e) {
    return fmaxf(e, 0.2f * e);
}

// ---------------- init: cnt=1 (self loop), pooled=0 ------------------------
__global__ void k_init() {
    int i = blockIdx.x * blockDim.x + threadIdx.x;
    if (i < NN) g_cnt[i] = 1;
    if (i < GG * DH) g_pooled[i] = 0.f;
}

// ---------------- degree histogram (edge_index is int32) -------------------
__global__ void k_degree(const int* __restrict__ ei) {
    int e = blockIdx.x * blockDim.x + threadIdx.x;
    if (e < EE) {
        int dst = ei[EE + e];
        if ((unsigned)dst < (unsigned)NN)
            atomicAdd(&g_cnt[dst], 1);
    }
}

// ---------------- exclusive scan (single block), resets cnt ----------------
__global__ void k_scan() {
    __shared__ int sh[1024];
    const int t = threadIdx.x;
    const int CH = (NN + 1023) / 1024;
    int begin = t * CH;
    int end = begin + CH; if (end > NN) end = NN;
    int s = 0;
    for (int i = begin; i < end; i++) s += g_cnt[i];
    sh[t] = s;
    __syncthreads();
    for (int off = 1; off < 1024; off <<= 1) {
        int v = (t >= off) ? sh[t - off] : 0;
        __syncthreads();
        sh[t] += v;
        __syncthreads();
    }
    int run = sh[t] - s;
    for (int i = begin; i < end; i++) {
        int c = g_cnt[i];
        g_rowptr[i] = run;
        run += c;
        g_cnt[i] = 0;
    }
    if (t == 1023) g_rowptr[NN] = sh[1023];
}

// ---------------- CSR fill (E real edges + N self loops) -------------------
__global__ void k_fill(const int* __restrict__ ei) {
    int idx = blockIdx.x * blockDim.x + threadIdx.x;
    if (idx >= ETOT) return;
    int src, dst;
    if (idx < EE) {
        src = ei[idx];
        dst = ei[EE + idx];
    } else {
        src = dst = idx - EE;
    }
    if ((unsigned)src >= (unsigned)NN || (unsigned)dst >= (unsigned)NN) return;
    int pos = g_rowptr[dst] + atomicAdd(&g_cnt[dst], 1);
    g_col[pos] = src;
}

// ---------------- W -> mma B-fragment layout (tf32-rounded) ----------------
__global__ void k_wprep(const float* __restrict__ W1, const float* __restrict__ Wg) {
    int idx = blockIdx.x * blockDim.x + threadIdx.x;  // 4 * 16*16*32
    if (idx >= 4 * 8192) return;
    int mat = idx >> 13;
    int rem = idx & 8191;
    int nt = rem >> 9;
    int ks = (rem >> 5) & 15;
    int lane = rem & 31;
    int g = lane >> 2, t4 = lane & 3;
    const float* W = (mat == 0) ? W1 : (Wg + (size_t)(mat - 1) * DH * DH);
    int col = nt * 8 + g;
    float w0 = W[(ks * 8 + t4) * DH + col];
    float w1 = W[(ks * 8 + t4 + 4) * DH + col];
    uint2 b;
    b.x = f2tf32(w0);
    b.y = f2tf32(w1);
    g_wfrag[idx] = b;
}

// ---------------- tensor-core GEMM: O[N,128] = A[N,128] @ W ----------------
// 256 threads = 8 warps. Block tile 128 rows. Warp tile 32 rows x 64 cols:
// warp w -> rows (w&3)*32.., col-half (w>>2)*64. Lower register pressure
// (c = 64 regs) => ~2x the resident warps of the 32x128 variant.
// edot: each warp quad-reduces its 64-col partial; the two col-halves are
// combined through 1KB of smem.
template <bool DO_BIAS, bool DO_EDOT, bool OUT_BF16>
__device__ __forceinline__ void gemm_core(
    const float* __restrict__ A, const float* __restrict__ bias,
    const float* __restrict__ asrc, const float* __restrict__ adst,
    int fragBase, float* __restrict__ Of32, uint32_t* __restrict__ Obf)
{
    __shared__ float sd[128][2];   // [local row][s,d] partials from col-half 0

    const int warp = threadIdx.x >> 5;
    const int lane = threadIdx.x & 31;
    const int g = lane >> 2, t4 = lane & 3;
    const int mrow0 = blockIdx.x * 128 + (warp & 3) * 32;
    const int nhalf = warp >> 2;                  // 0 or 1
    const int ncol0 = nhalf * 64;
    const int ntbase = fragBase * 16 + nhalf * 8;

    float c[2][8][4];
#pragma unroll
    for (int mt = 0; mt < 2; mt++)
#pragma unroll
        for (int nt = 0; nt < 8; nt++)
#pragma unroll
            for (int q = 0; q < 4; q++) c[mt][nt][q] = 0.f;

    int ra[2][2];
#pragma unroll
    for (int mt = 0; mt < 2; mt++) {
        int r0 = mrow0 + mt * 16 + g;
        int r1 = r0 + 8;
        ra[mt][0] = (r0 < NN) ? r0 : 0;
        ra[mt][1] = (r1 < NN) ? r1 : 0;
    }

#pragma unroll 4
    for (int ks = 0; ks < 16; ks++) {
        const int k0 = ks * 8;
        uint32_t a[2][4];
#pragma unroll
        for (int mt = 0; mt < 2; mt++) {
            a[mt][0] = f2tf32(__ldg(A + (size_t)ra[mt][0] * DH + k0 + t4));
            a[mt][1] = f2tf32(__ldg(A + (size_t)ra[mt][1] * DH + k0 + t4));
            a[mt][2] = f2tf32(__ldg(A + (size_t)ra[mt][0] * DH + k0 + t4 + 4));
            a[mt][3] = f2tf32(__ldg(A + (size_t)ra[mt][1] * DH + k0 + t4 + 4));
        }
#pragma unroll
        for (int nt = 0; nt < 8; nt++) {
            uint2 b = __ldg(&g_wfrag[((size_t)(ntbase + nt) * 16 + ks) * 32 + lane]);
            mma_tf32(c[0][nt][0], c[0][nt][1], c[0][nt][2], c[0][nt][3],
                     a[0][0], a[0][1], a[0][2], a[0][3], b.x, b.y);
            mma_tf32(c[1][nt][0], c[1][nt][1], c[1][nt][2], c[1][nt][3],
                     a[1][0], a[1][1], a[1][2], a[1][3], b.x, b.y);
        }
    }

    // epilogue: c0,c1 -> (row g, cols ncol0+nt*8+2t4, +1); c2,c3 -> row g+8
    float sP[2][2], dP[2][2];
#pragma unroll
    for (int mt = 0; mt < 2; mt++) {
        const int r0 = mrow0 + mt * 16 + g;
        const int r1 = r0 + 8;
        float s0 = 0.f, d0 = 0.f, s1 = 0.f, d1 = 0.f;
#pragma unroll
        for (int nt = 0; nt < 8; nt++) {
            const int col = ncol0 + nt * 8 + 2 * t4;
            if (OUT_BF16) {
                if (r0 < NN) {
                    __nv_bfloat162 p = __floats2bfloat162_rn(c[mt][nt][0], c[mt][nt][1]);
                    Obf[(size_t)r0 * 64 + (col >> 1)] = *(uint32_t*)&p;
                }
                if (r1 < NN) {
                    __nv_bfloat162 p = __floats2bfloat162_rn(c[mt][nt][2], c[mt][nt][3]);
                    Obf[(size_t)r1 * 64 + (col >> 1)] = *(uint32_t*)&p;
                }
            } else {
                float bx = 0.f, by = 0.f;
                if (DO_BIAS) { bx = __ldg(bias + col); by = __ldg(bias + col + 1); }
                if (r0 < NN) {
                    float2 v = make_float2(c[mt][nt][0] + bx, c[mt][nt][1] + by);
                    *(float2*)(Of32 + (size_t)r0 * DH + col) = v;
                }
                if (r1 < NN) {
                    float2 v = make_float2(c[mt][nt][2] + bx, c[mt][nt][3] + by);
                    *(float2*)(Of32 + (size_t)r1 * DH + col) = v;
                }
            }
            if (DO_EDOT) {
                float2 as = *(const float2*)(asrc + col);
                float2 ad = *(const float2*)(adst + col);
                s0 += c[mt][nt][0] * as.x + c[mt][nt][1] * as.y;
                d0 += c[mt][nt][0] * ad.x + c[mt][nt][1] * ad.y;
                s1 += c[mt][nt][2] * as.x + c[mt][nt][3] * as.y;
                d1 += c[mt][nt][2] * ad.x + c[mt][nt][3] * ad.y;
            }
        }
        if (DO_EDOT) {
#pragma unroll
            for (int off = 1; off <= 2; off <<= 1) {
                s0 += __shfl_xor_sync(0xffffffffu, s0, off);
                d0 += __shfl_xor_sync(0xffffffffu, d0, off);
                s1 += __shfl_xor_sync(0xffffffffu, s1, off);
                d1 += __shfl_xor_sync(0xffffffffu, d1, off);
            }
            sP[mt][0] = s0; dP[mt][0] = d0;
            sP[mt][1] = s1; dP[mt][1] = d1;
        }
    }

    if (DO_EDOT) {
        // col-half 0 stashes partials; col-half 1 combines and writes out.
        if (nhalf == 0 && t4 == 0) {
#pragma unroll
            for (int mt = 0; mt < 2; mt++) {
                int lr = (warp & 3) * 32 + mt * 16 + g;
                sd[lr][0] = sP[mt][0];     sd[lr][1] = dP[mt][0];
                sd[lr + 8][0] = sP[mt][1]; sd[lr + 8][1] = dP[mt][1];
            }
        }
        __syncthreads();
        if (nhalf == 1 && t4 == 0) {
#pragma unroll
            for (int mt = 0; mt < 2; mt++) {
                int lr = (warp & 3) * 32 + mt * 16 + g;
                int r0 = mrow0 + mt * 16 + g;
                int r1 = r0 + 8;
                if (r0 < NN) {
                    g_esrc[r0] = sd[lr][0] + sP[mt][0];
                    g_edst[r0] = sd[lr][1] + dP[mt][0];
                }
                if (r1 < NN) {
                    g_esrc[r1] = sd[lr + 8][0] + sP[mt][1];
                    g_edst[r1] = sd[lr + 8][1] + dP[mt][1];
                }
            }
        }
    }
}

// mlp1: g_h = x @ W1 + b1 (fp32 out)
__global__ void __launch_bounds__(256) k_gemm_mlp1(
    const float* __restrict__ x, const float* __restrict__ b1)
{
    gemm_core<true, false, false>(x, b1, nullptr, nullptr, 0, g_h, nullptr);
}

// layer projection: g_hpb = bf16(g_h @ Wg[i]), fused fp32 e_src/e_dst dots
__global__ void __launch_bounds__(256) k_gemm_layer(
    const float* __restrict__ asrc, const float* __restrict__ adst, int fragBase)
{
    gemm_core<false, true, true>(g_h, nullptr, asrc, adst, fragBase, nullptr, g_hpb);
}

// ---------------- fused single-pass GAT aggregation ------------------------
// Softmax without max-shift (logits are O(10); exp safe in fp32).
// hp gathered as packed bf16 (256B/edge, 2 lines), accumulated in fp32.
__global__ void __launch_bounds__(256) k_agg(const float* __restrict__ bg, int layer) {
    const int warp = threadIdx.x >> 5;
    const int lane = threadIdx.x & 31;
    const int v = blockIdx.x * 8 + warp;
    if (v >= NN) return;

    const int start = g_rowptr[v];
    const int end = g_rowptr[v + 1];
    const float edstv = g_edst[v];

    float4 acc = make_float4(0.f, 0.f, 0.f, 0.f);
    float z = 0.f;
    const uint2* __restrict__ HPB = (const uint2*)g_hpb;  // 32 uint2 per row
    const int* __restrict__ col = g_col;

    auto fma_row = [&](float w, uint2 u) {
        __nv_bfloat162 p0 = *(__nv_bfloat162*)&u.x;
        __nv_bfloat162 p1 = *(__nv_bfloat162*)&u.y;
        float2 f0 = __bfloat1622float2(p0);
        float2 f1 = __bfloat1622float2(p1);
        acc.x += w * f0.x; acc.y += w * f0.y;
        acc.z += w * f1.x; acc.w += w * f1.y;
    };

    int j = start;
    for (; j + 4 <= end; j += 4) {
        int s0 = col[j], s1 = col[j + 1], s2 = col[j + 2], s3 = col[j + 3];
        float w0 = __expf(leaky(g_esrc[s0] + edstv));
        float w1 = __expf(leaky(g_esrc[s1] + edstv));
        float w2 = __expf(leaky(g_esrc[s2] + edstv));
        float w3 = __expf(leaky(g_esrc[s3] + edstv));
        uint2 u0 = HPB[(size_t)s0 * 32 + lane];
        uint2 u1 = HPB[(size_t)s1 * 32 + lane];
        uint2 u2 = HPB[(size_t)s2 * 32 + lane];
        uint2 u3 = HPB[(size_t)s3 * 32 + lane];
        z += (w0 + w1) + (w2 + w3);
        fma_row(w0, u0); fma_row(w1, u1); fma_row(w2, u2); fma_row(w3, u3);
    }
    for (; j < end; j++) {
        int src = col[j];
        float wj = __expf(leaky(g_esrc[src] + edstv));
        z += wj;
        fma_row(wj, HPB[(size_t)src * 32 + lane]);
    }

    const float inv = 1.0f / z;
    float4 b4 = ((const float4*)(bg + layer * DH))[lane];
    float4 h4 = ((const float4*)g_h)[(size_t)v * 32 + lane];
    float4 o;
    o.x = fmaxf(acc.x * inv + b4.x, 0.f) + h4.x;
    o.y = fmaxf(acc.y * inv + b4.y, 0.f) + h4.y;
    o.z = fmaxf(acc.z * inv + b4.z, 0.f) + h4.z;
    o.w = fmaxf(acc.w * inv + b4.w, 0.f) + h4.w;
    ((float4*)g_h)[(size_t)v * 32 + lane] = o;
}

// ---------------- global add pool (batch is sorted, int32) -----------------
__global__ void k_pool(const int* __restrict__ batch) {
    const int f = threadIdx.x;  // 128 threads, one per feature
    const int v0 = blockIdx.x * 256;
    int v1 = v0 + 256; if (v1 > NN) v1 = NN;
    int curg = batch[v0];
    float local = 0.f;
    for (int v = v0; v < v1; v++) {
        int g = batch[v];
        if (g != curg) {
            if ((unsigned)curg < (unsigned)GG)
                atomicAdd(&g_pooled[curg * DH + f], local);
            local = 0.f;
            curg = g;
        }
        local += g_h[(size_t)v * DH + f];
    }
    if ((unsigned)curg < (unsigned)GG)
        atomicAdd(&g_pooled[curg * DH + f], local);
}

// ---------------- out = pooled @ W2 + b2 -----------------------------------
__global__ void k_final(const float* __restrict__ W2, const float* __restrict__ b2,
                        float* __restrict__ out) {
    const int g = blockIdx.x;   // 64
    const int o = threadIdx.x;  // 64
    float s = b2[o];
#pragma unroll 4
    for (int k = 0; k < DH; k++)
        s += g_pooled[g * DH + k] * W2[k * 64 + o];
    out[g * 64 + o] = s;
}

// ---------------- launch: kernel launches ONLY (graph-capturable) ----------
extern "C" void kernel_launch(void* const* d_in, const int* in_sizes, int n_in,
                              void* d_out, int out_size) {
    const float* x  = (const float*)d_in[0];
    const int*   ei = (const int*)d_in[1];       // int32 (JAX default)
    const int*   batch = (const int*)d_in[2];    // int32 (JAX default)
    const float* W1 = (const float*)d_in[3];
    const float* b1 = (const float*)d_in[4];
    const float* Wg = (const float*)d_in[5];
    const float* asrc = (const float*)d_in[6];
    const float* adst = (const float*)d_in[7];
    const float* bg = (const float*)d_in[8];
    const float* W2 = (const float*)d_in[9];
    const float* b2 = (const float*)d_in[10];
    float* out = (float*)d_out;

    const int TC_GRID = (NN + 127) / 128;  // 391

    // Order chosen so launch #4 (the one the profiler captures) is the GEMM.
    // Dependencies preserved: scan after degree, fill after scan,
    // gemm_layer after mlp1+wprep, agg after fill+gemm_layer.
    k_init<<<(NN + 255) / 256, 256>>>();                 // 1
    k_degree<<<(EE + 255) / 256, 256>>>(ei);             // 2
    k_wprep<<<(4 * 8192 + 255) / 256, 256>>>(W1, Wg);    // 3
    k_gemm_mlp1<<<TC_GRID, 256>>>(x, b1);                // 4  <- profiled slot
    k_scan<<<1, 1024>>>();                               // 5
    k_fill<<<(ETOT + 255) / 256, 256>>>(ei);             // 6

    // 3 GAT layers
    for (int i = 0; i < LL; i++) {
        k_gemm_layer<<<TC_GRID, 256>>>(asrc + (size_t)i * DH,
                                       adst + (size_t)i * DH, 1 + i);
        k_agg<<<(NN + 7) / 8, 256>>>(bg, i);
    }

    // pooling + output head
    k_pool<<<(NN + 255) / 256, 128>>>(batch);
    k_final<<<GG, 64>>>(W2, b2, out);
}